// round 3
// baseline (speedup 1.0000x reference)
#include <cuda_runtime.h>
#include <math.h>

// ---------------- problem constants ----------------
#define Bsz   16384
#define Wsz   5
#define Lsz   20
#define Esz   50
#define Vsz   100000
#define Csz   128
#define Hsz   4096
#define Osz   50
#define KPAD  256          // padded fc1 K (W*E = 250 -> 256)
#define NW    (Bsz*Wsz)    // 81920 word slots

// ---------------- device scratch (no allocs allowed) ----------------
__device__ float d_proj[3 * Csz * Esz];          // 19200
__device__ float d_g[Bsz * KPAD];                // 16.8 MB  (features, K-padded)
__device__ float d_w1p[Hsz * KPAD];              // 4 MB     (fc1_w K-padded)
__device__ float d_w2p[64 * Hsz];                // 1 MB     (fc2_w N-padded 50->64)
__device__ float d_b2p[64];
__device__ float d_h[(size_t)Bsz * Hsz];         // 268 MB   (tanh activations)

// ---------------- kernel 1: proj tables  proj[k][c][e] = sum_i conv_w[e,i,k]*char_emb[c,i]
__global__ void k_proj(const float* __restrict__ conv_w, const float* __restrict__ char_emb) {
    int tid = threadIdx.x;
    if (tid >= 150) return;
    int k = tid / 50, e = tid % 50;
    int c = blockIdx.x;
    float acc = 0.f;
#pragma unroll
    for (int i = 0; i < Esz; ++i)
        acc += conv_w[(e * Esz + i) * 3 + k] * char_emb[c * Esz + i];
    d_proj[k * (Csz * Esz) + c * Esz + e] = acc;
}

// ---------------- kernel 2a: pad fc1_w [4096,250] -> [4096,256]
__global__ void k_padw1(const float* __restrict__ w1) {
    int idx = blockIdx.x * blockDim.x + threadIdx.x;   // < 4096*256
    int n = idx >> 8, k = idx & 255;
    d_w1p[idx] = (k < 250) ? w1[n * 250 + k] : 0.f;
}

// ---------------- kernel 2b: pad fc2_w [50,4096] -> [64,4096], bias pad
__global__ void k_padw2(const float* __restrict__ w2, const float* __restrict__ b2) {
    int idx = blockIdx.x * blockDim.x + threadIdx.x;   // < 64*4096
    int o = idx >> 12, k = idx & 4095;
    d_w2p[idx] = (o < 50) ? w2[o * Hsz + k] : 0.f;
    if (idx < 64) d_b2p[idx] = (idx < 50) ? b2[idx] : 0.f;
}

// ---------------- kernel 3: features
// g[b, w*50+e] = word_emb[x,e] + max_l( proj0[c_{l-1},e]+proj1[c_l,e]+proj2[c_{l+1},e] ) + conv_b[e]
// proj[·][0]=0 plays the role of conv zero-padding (char_emb[0]==0).
__global__ void k_feat(const int* __restrict__ x, const int* __restrict__ w2c,
                       const float* __restrict__ wemb, const float* __restrict__ convb) {
    extern __shared__ float smem[];
    float* sp   = smem;            // 19200 floats: proj tables
    float* scb  = smem + 19200;    // 64 floats: conv bias
    int*   scid = (int*)(smem + 19264);  // 8 groups * 20 char ids

    int tid = threadIdx.x;
    for (int i = tid; i < 19200; i += 512) sp[i] = d_proj[i];
    if (tid < 50) scb[tid] = convb[tid];
    __syncthreads();

    int grp = tid >> 6, lane = tid & 63;
    int base = blockIdx.x * 32 + grp * 4;   // this group's first word slot

    for (int it = 0; it < 4; ++it) {
        int widx = base + it;               // < 81920
        int xv = x[widx];
        if (lane < Lsz) scid[grp * Lsz + lane] = w2c[xv * Lsz + lane];
        __syncthreads();

        int b = widx / Wsz, w = widx - b * Wsz;
        if (lane < Esz) {
            const int* cid = scid + grp * Lsz;
            float m = -1e30f;
            int cp = 0, cc = cid[0];
#pragma unroll
            for (int l = 0; l < Lsz; ++l) {
                int cn = (l < Lsz - 1) ? cid[l + 1] : 0;
                float s = sp[cp * Esz + lane]
                        + sp[6400 + cc * Esz + lane]
                        + sp[12800 + cn * Esz + lane];
                m = fmaxf(m, s);
                cp = cc; cc = cn;
            }
            d_g[b * KPAD + w * Esz + lane] = wemb[xv * Esz + lane] + m + scb[lane];
        }
        if (lane >= 50 && lane < 56 && w == 0)          // zero the K pad [250,256)
            d_g[b * KPAD + 250 + (lane - 50)] = 0.f;
        __syncthreads();
    }
}

// ---------------- kernel 4: fc1  h = tanh(g @ w1p^T + b1)   [16384,256]x[4096,256]
__global__ __launch_bounds__(256) void k_fc1(const float* __restrict__ b1) {
    __shared__ float As[16][128];
    __shared__ float Bs[16][128];
    int tid = threadIdx.x;
    int tx = tid & 15, ty = tid >> 4;
    int bm = blockIdx.y << 7, bn = blockIdx.x << 7;

    float acc[8][8];
#pragma unroll
    for (int i = 0; i < 8; ++i)
#pragma unroll
        for (int j = 0; j < 8; ++j) acc[i][j] = 0.f;

    for (int kk = 0; kk < KPAD; kk += 16) {
#pragma unroll
        for (int p = 0; p < 2; ++p) {
            int fi = tid + (p << 8);
            int m = fi >> 2, k4 = (fi & 3) << 2;
            float4 va = *(const float4*)&d_g[(bm + m) * KPAD + kk + k4];
            As[k4 + 0][m] = va.x; As[k4 + 1][m] = va.y;
            As[k4 + 2][m] = va.z; As[k4 + 3][m] = va.w;
            float4 vb = *(const float4*)&d_w1p[(bn + m) * KPAD + kk + k4];
            Bs[k4 + 0][m] = vb.x; Bs[k4 + 1][m] = vb.y;
            Bs[k4 + 2][m] = vb.z; Bs[k4 + 3][m] = vb.w;
        }
        __syncthreads();
#pragma unroll
        for (int k = 0; k < 16; ++k) {
            float4 a0 = *(float4*)&As[k][ty << 3];
            float4 a1 = *(float4*)&As[k][(ty << 3) + 4];
            float4 b0 = *(float4*)&Bs[k][tx << 3];
            float4 b1f = *(float4*)&Bs[k][(tx << 3) + 4];
            float av[8] = {a0.x, a0.y, a0.z, a0.w, a1.x, a1.y, a1.z, a1.w};
            float bv[8] = {b0.x, b0.y, b0.z, b0.w, b1f.x, b1f.y, b1f.z, b1f.w};
#pragma unroll
            for (int i = 0; i < 8; ++i)
#pragma unroll
                for (int j = 0; j < 8; ++j) acc[i][j] += av[i] * bv[j];
        }
        __syncthreads();
    }

#pragma unroll
    for (int i = 0; i < 8; ++i) {
        int row = bm + (ty << 3) + i;
#pragma unroll
        for (int j = 0; j < 8; j += 4) {
            int col = bn + (tx << 3) + j;
            float4 o;
            o.x = tanhf(acc[i][j + 0] + b1[col + 0]);
            o.y = tanhf(acc[i][j + 1] + b1[col + 1]);
            o.z = tanhf(acc[i][j + 2] + b1[col + 2]);
            o.w = tanhf(acc[i][j + 3] + b1[col + 3]);
            *(float4*)&d_h[(size_t)row * Hsz + col] = o;
        }
    }
}

// ---------------- kernel 5: fc2 + softmax   [16384,4096] x [64,4096] -> softmax over 50
__global__ __launch_bounds__(256) void k_fc2(float* __restrict__ out) {
    __shared__ float As[16][64];
    __shared__ float Bs[16][64];
    __shared__ float sc[64][65];       // 64 cols written; padded to 65
    int tid = threadIdx.x;
    int tx = tid & 15, ty = tid >> 4;
    int bm = blockIdx.x << 6;

    float acc[4][4];
#pragma unroll
    for (int i = 0; i < 4; ++i)
#pragma unroll
        for (int j = 0; j < 4; ++j) acc[i][j] = 0.f;

    int m = tid >> 2, k4 = (tid & 3) << 2;
    for (int kk = 0; kk < Hsz; kk += 16) {
        float4 va = *(const float4*)&d_h[(size_t)(bm + m) * Hsz + kk + k4];
        As[k4 + 0][m] = va.x; As[k4 + 1][m] = va.y;
        As[k4 + 2][m] = va.z; As[k4 + 3][m] = va.w;
        float4 vb = *(const float4*)&d_w2p[m * Hsz + kk + k4];
        Bs[k4 + 0][m] = vb.x; Bs[k4 + 1][m] = vb.y;
        Bs[k4 + 2][m] = vb.z; Bs[k4 + 3][m] = vb.w;
        __syncthreads();
#pragma unroll
        for (int k = 0; k < 16; ++k) {
            float4 a = *(float4*)&As[k][ty << 2];
            float4 b = *(float4*)&Bs[k][tx << 2];
            float av[4] = {a.x, a.y, a.z, a.w};
            float bv[4] = {b.x, b.y, b.z, b.w};
#pragma unroll
            for (int i = 0; i < 4; ++i)
#pragma unroll
                for (int j = 0; j < 4; ++j) acc[i][j] += av[i] * bv[j];
        }
        __syncthreads();
    }

#pragma unroll
    for (int i = 0; i < 4; ++i)
#pragma unroll
        for (int j = 0; j < 4; ++j)
            sc[(ty << 2) + i][(tx << 2) + j] = acc[i][j] + d_b2p[(tx << 2) + j];
    __syncthreads();

    if (tid < 64) {
        int r = tid;
        float mx = -1e30f;
#pragma unroll
        for (int c = 0; c < Osz; ++c) mx = fmaxf(mx, sc[r][c]);
        float s = 0.f;
#pragma unroll
        for (int c = 0; c < Osz; ++c) {
            float e = expf(sc[r][c] - mx);
            sc[r][c] = e;
            s += e;
        }
        float inv = 1.f / s;
        int rowbase = (bm + r) * Osz;
#pragma unroll
        for (int c = 0; c < Osz; ++c) out[rowbase + c] = sc[r][c] * inv;
    }
}

// ---------------- launcher ----------------
extern "C" void kernel_launch(void* const* d_in, const int* in_sizes, int n_in,
                              void* d_out, int out_size) {
    // Resolve inputs by element count (robust to harness input ordering).
    // Counts: x=81920, w2c=2000000, wemb=5000000, cemb=6400, convw=7500,
    // w1=1024000, b1=4096, w2=204800, convb=b2=50 (convb first in both
    // insertion and alphabetical order).
    const int *x = 0, *w2c = 0;
    const float *wemb = 0, *cemb = 0, *convw = 0, *convb = 0;
    const float *w1 = 0, *b1 = 0, *w2 = 0, *b2 = 0;
    int seen50 = 0;
    for (int i = 0; i < n_in; ++i) {
        int s = in_sizes[i];
        if      (s == Bsz * Wsz)     x     = (const int*)d_in[i];
        else if (s == Vsz * Lsz)     w2c   = (const int*)d_in[i];
        else if (s == Vsz * Esz)     wemb  = (const float*)d_in[i];
        else if (s == Csz * Esz)     cemb  = (const float*)d_in[i];
        else if (s == Esz * Esz * 3) convw = (const float*)d_in[i];
        else if (s == Hsz * 250)     w1    = (const float*)d_in[i];
        else if (s == Hsz)           b1    = (const float*)d_in[i];
        else if (s == Osz * Hsz)     w2    = (const float*)d_in[i];
        else if (s == 50) {
            if (seen50++ == 0) convb = (const float*)d_in[i];
            else               b2    = (const float*)d_in[i];
        }
    }
    float* out = (float*)d_out;

    // prep (tiny)
    k_proj <<<Csz, 160>>>(convw, cemb);
    k_padw1<<<(Hsz * KPAD) / 256, 256>>>(w1);
    k_padw2<<<(64 * Hsz) / 256, 256>>>(w2, b2);

    // features (char-CNN collapsed to table gathers)
    static bool attr_set = false;
    if (!attr_set) {
        cudaFuncSetAttribute(k_feat, cudaFuncAttributeMaxDynamicSharedMemorySize, 80000);
        attr_set = true;
    }
    size_t feat_smem = (19200 + 64 + 8 * Lsz) * sizeof(float);
    k_feat<<<NW / 32, 512, feat_smem>>>(x, w2c, wemb, convb);

    // fc1: 16384x4096x256 sgemm + tanh
    k_fc1<<<dim3(Hsz / 128, Bsz / 128), 256>>>(b1);

    // fc2 + softmax fused
    k_fc2<<<Bsz / 64, 256>>>(out);
}

// round 6
// speedup vs baseline: 1.6235x; 1.6235x over previous
#include <cuda_runtime.h>
#include <cuda_bf16.h>
#include <math.h>
#include <stdint.h>

// ---------------- problem constants ----------------
#define Bsz   16384
#define Wsz   5
#define Lsz   20
#define Esz   50
#define Vsz   100000
#define Csz   128
#define Hsz   4096
#define Osz   50
#define NW    (Bsz*Wsz)

// fc1 split-bf16 GEMM: K'' = 3*256 (hi*hi | hi*lo | lo*hi baked into K)
#define KTRIP 768

// ---------------- device scratch ----------------
__device__ float d_proj[3 * Csz * Esz];
__device__ __align__(16) __nv_bfloat16 d_gA[Bsz * KTRIP];     // 25 MB  A'' bf16
__device__ __align__(16) __nv_bfloat16 d_w1B[Hsz * KTRIP];    // 6 MB   B'' bf16
__device__ float d_w2p[64 * Hsz];
__device__ float d_b2p[64];
__device__ float d_h[(size_t)Bsz * Hsz];                      // 268 MB

// ---------------- helpers ----------------
__device__ __forceinline__ uint32_t smem_u32(const void* p) {
    uint32_t a;
    asm("{ .reg .u64 t; cvta.to.shared.u64 t, %1; cvt.u32.u64 %0, t; }" : "=r"(a) : "l"(p));
    return a;
}
#define SWZ128(o) ((o) ^ ((((uint32_t)(o)) >> 3) & 0x70))
__device__ __forceinline__ void cp16(uint32_t saddr, const void* g) {
    asm volatile("cp.async.cg.shared.global [%0], [%1], 16;" :: "r"(saddr), "l"(g));
}
#define CP_COMMIT() asm volatile("cp.async.commit_group;" ::: "memory")
#define CP_WAIT(n)  asm volatile("cp.async.wait_group %0;" :: "n"(n) : "memory")

__device__ __forceinline__ void ldm_x4(uint32_t* r, uint32_t saddr) {
    asm volatile("ldmatrix.sync.aligned.m8n8.x4.shared.b16 {%0,%1,%2,%3}, [%4];"
                 : "=r"(r[0]), "=r"(r[1]), "=r"(r[2]), "=r"(r[3]) : "r"(saddr));
}
__device__ __forceinline__ void mma16816(float* c, const uint32_t* a, uint32_t b0, uint32_t b1) {
    asm volatile("mma.sync.aligned.m16n8k16.row.col.f32.bf16.bf16.f32 "
                 "{%0,%1,%2,%3}, {%4,%5,%6,%7}, {%8,%9}, {%0,%1,%2,%3};"
                 : "+f"(c[0]), "+f"(c[1]), "+f"(c[2]), "+f"(c[3])
                 : "r"(a[0]), "r"(a[1]), "r"(a[2]), "r"(a[3]), "r"(b0), "r"(b1));
}

// ---------------- kernel 1: proj tables ----------------
__global__ void k_proj(const float* __restrict__ conv_w, const float* __restrict__ char_emb) {
    int tid = threadIdx.x;
    if (tid >= 150) return;
    int k = tid / 50, e = tid % 50;
    int c = blockIdx.x;
    float acc = 0.f;
#pragma unroll
    for (int i = 0; i < Esz; ++i)
        acc += conv_w[(e * Esz + i) * 3 + k] * char_emb[c * Esz + i];
    d_proj[k * (Csz * Esz) + c * Esz + e] = acc;
}

// ---------------- kernel 2a: fc1_w -> split-bf16 K-tripled [4096,768] ----------------
__global__ void k_prepw1(const float* __restrict__ w1) {
    int idx = blockIdx.x * blockDim.x + threadIdx.x;
    int n = idx >> 8, k = idx & 255;
    float v = (k < 250) ? w1[n * 250 + k] : 0.f;
    __nv_bfloat16 hi = __float2bfloat16(v);
    __nv_bfloat16 lo = __float2bfloat16(v - __bfloat162float(hi));
    d_w1B[n * KTRIP + k]       = hi;
    d_w1B[n * KTRIP + 256 + k] = lo;
    d_w1B[n * KTRIP + 512 + k] = hi;
}

// ---------------- kernel 2b: pad fc2_w ----------------
__global__ void k_padw2(const float* __restrict__ w2, const float* __restrict__ b2) {
    int idx = blockIdx.x * blockDim.x + threadIdx.x;
    int o = idx >> 12, k = idx & 4095;
    d_w2p[idx] = (o < 50) ? w2[o * Hsz + k] : 0.f;
    if (idx < 64) d_b2p[idx] = (idx < 50) ? b2[idx] : 0.f;
}

// ---------------- kernel 3: features -> split-bf16 K-tripled A'' ----------------
__global__ void k_feat(const int* __restrict__ x, const int* __restrict__ w2c,
                       const float* __restrict__ wemb, const float* __restrict__ convb) {
    extern __shared__ float smf[];
    float* sp   = smf;
    float* scb  = smf + 19200;
    int*   scid = (int*)(smf + 19264);

    int tid = threadIdx.x;
    for (int i = tid; i < 19200; i += 512) sp[i] = d_proj[i];
    if (tid < 50) scb[tid] = convb[tid];
    __syncthreads();

    int grp = tid >> 6, lane = tid & 63;
    int base = blockIdx.x * 32 + grp * 4;

    const __nv_bfloat16 z = __float2bfloat16(0.f);
    for (int it = 0; it < 4; ++it) {
        int widx = base + it;
        int xv = x[widx];
        if (lane < Lsz) scid[grp * Lsz + lane] = w2c[xv * Lsz + lane];
        __syncthreads();

        int b = widx / Wsz, w = widx - b * Wsz;
        if (lane < Esz) {
            const int* cid = scid + grp * Lsz;
            float m = -1e30f;
            int cp = 0, cc = cid[0];
#pragma unroll
            for (int l = 0; l < Lsz; ++l) {
                int cn = (l < Lsz - 1) ? cid[l + 1] : 0;
                float s = sp[cp * Esz + lane]
                        + sp[6400 + cc * Esz + lane]
                        + sp[12800 + cn * Esz + lane];
                m = fmaxf(m, s);
                cp = cc; cc = cn;
            }
            float v = wemb[xv * Esz + lane] + m + scb[lane];
            __nv_bfloat16 hi = __float2bfloat16(v);
            __nv_bfloat16 lo = __float2bfloat16(v - __bfloat162float(hi));
            int col = w * Esz + lane;
            d_gA[b * KTRIP + col]       = hi;
            d_gA[b * KTRIP + 256 + col] = hi;
            d_gA[b * KTRIP + 512 + col] = lo;
        }
        if (lane >= 50 && lane < 56 && w == 0) {
            int col = 200 + lane;   // 250..255
            d_gA[b * KTRIP + col]       = z;
            d_gA[b * KTRIP + 256 + col] = z;
            d_gA[b * KTRIP + 512 + col] = z;
        }
        __syncthreads();
    }
}

// ---------------- kernel 4: fc1 via mma.sync bf16  h = tanh(A''@B''^T + b1) ------
// CTA tile 128(M)x128(N), K=768 in 12 slabs of 64 bf16. 8 warps = 2(M)x4(N);
// warp tile 64x32. Double-buffered cp.async smem, SW128 swizzle, ldmatrix.x4.
// smem: buf{0,1} x (A 16KB + B 16KB) = 64KB dynamic.
#define FC1_SMEM 65536
__global__ __launch_bounds__(256) void k_fc1m(const float* __restrict__ b1) {
    extern __shared__ __align__(1024) char smc[];
    uint32_t sbase = smem_u32(smc);
    int tid = threadIdx.x;
    int lane = tid & 31, warp = tid >> 5;
    int wm = warp & 1, wn = warp >> 1;          // 2 x 4 warp grid
    int bm = blockIdx.y << 7, bn = blockIdx.x << 7;

    float acc[4][4][4];
#pragma unroll
    for (int i = 0; i < 4; ++i)
#pragma unroll
        for (int j = 0; j < 4; ++j)
#pragma unroll
            for (int q = 0; q < 4; ++q) acc[i][j][q] = 0.f;

    const char* gA = (const char*)d_gA;
    const char* gB = (const char*)d_w1B;

    // ldmatrix lane geometry (same for A and B tiles): row-in-16 + 16B chunk
    int lrow  = (lane & 7) + ((lane >> 3) & 1) * 8;   // 0..15
    int lchnk = (lane >> 4) << 4;                      // 0 or 16 bytes
    uint32_t lsw = (uint32_t)((lane & 7) << 4);        // swizzle XOR for this lane

    // stage slab s into buffer buf
    auto stage = [&](int s, int buf) {
        uint32_t ab = sbase + buf * 32768;
        uint32_t bb = ab + 16384;
        int koff = s * 128;                            // bytes into K''
#pragma unroll
        for (int i = 0; i < 4; ++i) {
            int idx = tid + (i << 8);
            int r = idx >> 3, c = (idx & 7) << 4;
            cp16(ab + SWZ128(r * 128 + c), gA + (size_t)(bm + r) * (KTRIP * 2) + koff + c);
        }
#pragma unroll
        for (int i = 0; i < 4; ++i) {
            int idx = tid + (i << 8);
            int r = idx >> 3, c = (idx & 7) << 4;
            cp16(bb + SWZ128(r * 128 + c), gB + (size_t)(bn + r) * (KTRIP * 2) + koff + c);
        }
    };

    stage(0, 0); CP_COMMIT();

    for (int s = 0; s < 12; ++s) {
        int buf = s & 1;
        if (s < 11) { stage(s + 1, buf ^ 1); CP_COMMIT(); CP_WAIT(1); }
        else        { CP_WAIT(0); }
        __syncthreads();

        uint32_t ab = sbase + buf * 32768;
        uint32_t bb = ab + 16384;
        // per-lane fixed row offsets
        uint32_t arow[4], brow[2];
#pragma unroll
        for (int mt = 0; mt < 4; ++mt)
            arow[mt] = ab + (uint32_t)((wm << 6) + (mt << 4) + lrow) * 128;
#pragma unroll
        for (int np = 0; np < 2; ++np)
            brow[np] = bb + (uint32_t)((wn << 5) + (np << 4) + lrow) * 128;

#pragma unroll
        for (int kb = 0; kb < 4; ++kb) {               // 4 k-steps of 16 bf16
            uint32_t koffb = (uint32_t)(kb * 32 + lchnk) ^ lsw;
            uint32_t af[4][4];
#pragma unroll
            for (int mt = 0; mt < 4; ++mt) ldm_x4(af[mt], arow[mt] + koffb);
            uint32_t bf[2][4];
#pragma unroll
            for (int np = 0; np < 2; ++np) ldm_x4(bf[np], brow[np] + koffb);
#pragma unroll
            for (int mt = 0; mt < 4; ++mt) {
#pragma unroll
                for (int np = 0; np < 2; ++np) {
                    // ntile np*2   = {m0, m2}; ntile np*2+1 = {m1, m3}
                    mma16816(acc[mt][np * 2],     af[mt], bf[np][0], bf[np][2]);
                    mma16816(acc[mt][np * 2 + 1], af[mt], bf[np][1], bf[np][3]);
                }
            }
        }
        __syncthreads();
    }

    // epilogue: c0,c1 -> row lane>>2, cols 2*(lane&3)+{0,1}; c2,c3 -> row+8
    int r0 = lane >> 2, c0 = (lane & 3) << 1;
#pragma unroll
    for (int mt = 0; mt < 4; ++mt) {
        int row = bm + (wm << 6) + (mt << 4) + r0;
        float* h0 = d_h + (size_t)row * Hsz;
        float* h1 = d_h + (size_t)(row + 8) * Hsz;
#pragma unroll
        for (int nt = 0; nt < 4; ++nt) {
            int col = bn + (wn << 5) + (nt << 3) + c0;
            float bias0 = b1[col], bias1 = b1[col + 1];
            float2 o0, o1;
            o0.x = tanhf(acc[mt][nt][0] + bias0);
            o0.y = tanhf(acc[mt][nt][1] + bias1);
            o1.x = tanhf(acc[mt][nt][2] + bias0);
            o1.y = tanhf(acc[mt][nt][3] + bias1);
            *(float2*)(h0 + col) = o0;
            *(float2*)(h1 + col) = o1;
        }
    }
}

// ---------------- kernel 5: fc2 + softmax ----------------
__global__ __launch_bounds__(256) void k_fc2(float* __restrict__ out) {
    __shared__ float As[16][64];
    __shared__ float Bs[16][64];
    __shared__ float sc[64][65];
    int tid = threadIdx.x;
    int tx = tid & 15, ty = tid >> 4;
    int bm = blockIdx.x << 6;

    float acc[4][4];
#pragma unroll
    for (int i = 0; i < 4; ++i)
#pragma unroll
        for (int j = 0; j < 4; ++j) acc[i][j] = 0.f;

    int m = tid >> 2, k4 = (tid & 3) << 2;
    for (int kk = 0; kk < Hsz; kk += 16) {
        float4 va = *(const float4*)&d_h[(size_t)(bm + m) * Hsz + kk + k4];
        As[k4 + 0][m] = va.x; As[k4 + 1][m] = va.y;
        As[k4 + 2][m] = va.z; As[k4 + 3][m] = va.w;
        float4 vb = *(const float4*)&d_w2p[m * Hsz + kk + k4];
        Bs[k4 + 0][m] = vb.x; Bs[k4 + 1][m] = vb.y;
        Bs[k4 + 2][m] = vb.z; Bs[k4 + 3][m] = vb.w;
        __syncthreads();
#pragma unroll
        for (int k = 0; k < 16; ++k) {
            float4 a = *(float4*)&As[k][ty << 2];
            float4 b = *(float4*)&Bs[k][tx << 2];
            float av[4] = {a.x, a.y, a.z, a.w};
            float bv[4] = {b.x, b.y, b.z, b.w};
#pragma unroll
            for (int i = 0; i < 4; ++i)
#pragma unroll
                for (int j = 0; j < 4; ++j) acc[i][j] += av[i] * bv[j];
        }
        __syncthreads();
    }

#pragma unroll
    for (int i = 0; i < 4; ++i)
#pragma unroll
        for (int j = 0; j < 4; ++j)
            sc[(ty << 2) + i][(tx << 2) + j] = acc[i][j] + d_b2p[(tx << 2) + j];
    __syncthreads();

    if (tid < 64) {
        int r = tid;
        float mx = -1e30f;
#pragma unroll
        for (int c = 0; c < Osz; ++c) mx = fmaxf(mx, sc[r][c]);
        float s = 0.f;
#pragma unroll
        for (int c = 0; c < Osz; ++c) {
            float e = expf(sc[r][c] - mx);
            sc[r][c] = e;
            s += e;
        }
        float inv = 1.f / s;
        int rowbase = (bm + r) * Osz;
#pragma unroll
        for (int c = 0; c < Osz; ++c) out[rowbase + c] = sc[r][c] * inv;
    }
}

// ---------------- launcher ----------------
extern "C" void kernel_launch(void* const* d_in, const int* in_sizes, int n_in,
                              void* d_out, int out_size) {
    const int *x = 0, *w2c = 0;
    const float *wemb = 0, *cemb = 0, *convw = 0, *convb = 0;
    const float *w1 = 0, *b1 = 0, *w2 = 0, *b2 = 0;
    int seen50 = 0;
    for (int i = 0; i < n_in; ++i) {
        int s = in_sizes[i];
        if      (s == Bsz * Wsz)     x     = (const int*)d_in[i];
        else if (s == Vsz * Lsz)     w2c   = (const int*)d_in[i];
        else if (s == Vsz * Esz)     wemb  = (const float*)d_in[i];
        else if (s == Csz * Esz)     cemb  = (const float*)d_in[i];
        else if (s == Esz * Esz * 3) convw = (const float*)d_in[i];
        else if (s == Hsz * 250)     w1    = (const float*)d_in[i];
        else if (s == Hsz)           b1    = (const float*)d_in[i];
        else if (s == Osz * Hsz)     w2    = (const float*)d_in[i];
        else if (s == 50) {
            if (seen50++ == 0) convb = (const float*)d_in[i];
            else               b2    = (const float*)d_in[i];
        }
    }
    float* out = (float*)d_out;

    static bool attr_set = false;
    if (!attr_set) {
        cudaFuncSetAttribute(k_feat,  cudaFuncAttributeMaxDynamicSharedMemorySize, 80000);
        cudaFuncSetAttribute(k_fc1m,  cudaFuncAttributeMaxDynamicSharedMemorySize, FC1_SMEM);
        attr_set = true;
    }

    // prep (tiny)
    k_proj  <<<Csz, 160>>>(convw, cemb);
    k_prepw1<<<Hsz, 256>>>(w1);
    k_padw2 <<<(64 * Hsz) / 256, 256>>>(w2, b2);

    // features -> split-bf16 A''
    size_t feat_smem = (19200 + 64 + 8 * Lsz) * sizeof(float);
    k_feat<<<NW / 32, 512, feat_smem>>>(x, w2c, wemb, convb);

    // fc1: mma.sync bf16 split GEMM, M=16384 N=4096 K=768
    k_fc1m<<<dim3(Hsz / 128, Bsz / 128), 256, FC1_SMEM>>>(b1);

    // fc2 + softmax fused (FFMA, next target)
    k_fc2<<<Bsz / 64, 256>>>(out);
}

// round 7
// speedup vs baseline: 2.2156x; 1.3647x over previous
#include <cuda_runtime.h>
#include <cuda_bf16.h>
#include <math.h>
#include <stdint.h>

// ---------------- problem constants ----------------
#define Bsz   16384
#define Wsz   5
#define Lsz   20
#define Esz   50
#define Vsz   100000
#define Csz   128
#define Hsz   4096
#define Osz   50
#define NW    (Bsz*Wsz)

// fc1 split-bf16 GEMM: K'' = 3*256 (hi*hi | hi*lo | lo*hi baked into K)
#define KTRIP 768

// ---------------- device scratch ----------------
__device__ float d_proj[3 * Csz * Esz];
__device__ __align__(16) __nv_bfloat16 d_gA[Bsz * KTRIP];        // 25 MB  A'' bf16
__device__ __align__(16) __nv_bfloat16 d_w1B[Hsz * KTRIP];       // 6 MB   B'' bf16
__device__ __align__(16) __nv_bfloat16 d_hh[(size_t)Bsz * Hsz];  // 134 MB h hi
__device__ __align__(16) __nv_bfloat16 d_hl[(size_t)Bsz * Hsz];  // 134 MB h lo
__device__ __align__(16) __nv_bfloat16 d_w2h[64 * Hsz];          // 512 KB
__device__ __align__(16) __nv_bfloat16 d_w2l[64 * Hsz];          // 512 KB
__device__ float d_b2p[64];

// ---------------- helpers ----------------
__device__ __forceinline__ uint32_t smem_u32(const void* p) {
    uint32_t a;
    asm("{ .reg .u64 t; cvta.to.shared.u64 t, %1; cvt.u32.u64 %0, t; }" : "=r"(a) : "l"(p));
    return a;
}
#define SWZ128(o) ((o) ^ ((((uint32_t)(o)) >> 3) & 0x70))
__device__ __forceinline__ void cp16(uint32_t saddr, const void* g) {
    asm volatile("cp.async.cg.shared.global [%0], [%1], 16;" :: "r"(saddr), "l"(g));
}
#define CP_COMMIT() asm volatile("cp.async.commit_group;" ::: "memory")
#define CP_WAIT(n)  asm volatile("cp.async.wait_group %0;" :: "n"(n) : "memory")

__device__ __forceinline__ void ldm_x4(uint32_t* r, uint32_t saddr) {
    asm volatile("ldmatrix.sync.aligned.m8n8.x4.shared.b16 {%0,%1,%2,%3}, [%4];"
                 : "=r"(r[0]), "=r"(r[1]), "=r"(r[2]), "=r"(r[3]) : "r"(saddr));
}
__device__ __forceinline__ void mma16816(float* c, const uint32_t* a, uint32_t b0, uint32_t b1) {
    asm volatile("mma.sync.aligned.m16n8k16.row.col.f32.bf16.bf16.f32 "
                 "{%0,%1,%2,%3}, {%4,%5,%6,%7}, {%8,%9}, {%0,%1,%2,%3};"
                 : "+f"(c[0]), "+f"(c[1]), "+f"(c[2]), "+f"(c[3])
                 : "r"(a[0]), "r"(a[1]), "r"(a[2]), "r"(a[3]), "r"(b0), "r"(b1));
}

// ---------------- kernel 1: proj tables ----------------
__global__ void k_proj(const float* __restrict__ conv_w, const float* __restrict__ char_emb) {
    int tid = threadIdx.x;
    if (tid >= 150) return;
    int k = tid / 50, e = tid % 50;
    int c = blockIdx.x;
    float acc = 0.f;
#pragma unroll
    for (int i = 0; i < Esz; ++i)
        acc += conv_w[(e * Esz + i) * 3 + k] * char_emb[c * Esz + i];
    d_proj[k * (Csz * Esz) + c * Esz + e] = acc;
}

// ---------------- kernel 2a: fc1_w -> split-bf16 K-tripled [4096,768] ----------------
__global__ void k_prepw1(const float* __restrict__ w1) {
    int idx = blockIdx.x * blockDim.x + threadIdx.x;
    int n = idx >> 8, k = idx & 255;
    float v = (k < 250) ? w1[n * 250 + k] : 0.f;
    __nv_bfloat16 hi = __float2bfloat16(v);
    __nv_bfloat16 lo = __float2bfloat16(v - __bfloat162float(hi));
    d_w1B[n * KTRIP + k]       = hi;
    d_w1B[n * KTRIP + 256 + k] = lo;
    d_w1B[n * KTRIP + 512 + k] = hi;
}

// ---------------- kernel 2b: fc2_w -> split bf16 [64,4096] + bias pad ----------------
__global__ void k_prepw2(const float* __restrict__ w2, const float* __restrict__ b2) {
    int idx = blockIdx.x * blockDim.x + threadIdx.x;   // < 64*4096
    int o = idx >> 12;
    float v = (o < 50) ? w2[o * Hsz + (idx & 4095)] : 0.f;
    __nv_bfloat16 hi = __float2bfloat16(v);
    __nv_bfloat16 lo = __float2bfloat16(v - __bfloat162float(hi));
    d_w2h[idx] = hi;
    d_w2l[idx] = lo;
    if (idx < 64) d_b2p[idx] = (idx < 50) ? b2[idx] : 0.f;
}

// ---------------- kernel 3: features -> split-bf16 K-tripled A'' ----------------
__global__ void k_feat(const int* __restrict__ x, const int* __restrict__ w2c,
                       const float* __restrict__ wemb, const float* __restrict__ convb) {
    extern __shared__ float smf[];
    float* sp   = smf;
    float* scb  = smf + 19200;
    int*   scid = (int*)(smf + 19264);

    int tid = threadIdx.x;
    for (int i = tid; i < 19200; i += 512) sp[i] = d_proj[i];
    if (tid < 50) scb[tid] = convb[tid];
    __syncthreads();

    int grp = tid >> 6, lane = tid & 63;
    int base = blockIdx.x * 32 + grp * 4;

    const __nv_bfloat16 z = __float2bfloat16(0.f);
    for (int it = 0; it < 4; ++it) {
        int widx = base + it;
        int xv = x[widx];
        if (lane < Lsz) scid[grp * Lsz + lane] = w2c[xv * Lsz + lane];
        __syncthreads();

        int b = widx / Wsz, w = widx - b * Wsz;
        if (lane < Esz) {
            const int* cid = scid + grp * Lsz;
            float m = -1e30f;
            int cp = 0, cc = cid[0];
#pragma unroll
            for (int l = 0; l < Lsz; ++l) {
                int cn = (l < Lsz - 1) ? cid[l + 1] : 0;
                float s = sp[cp * Esz + lane]
                        + sp[6400 + cc * Esz + lane]
                        + sp[12800 + cn * Esz + lane];
                m = fmaxf(m, s);
                cp = cc; cc = cn;
            }
            float v = wemb[xv * Esz + lane] + m + scb[lane];
            __nv_bfloat16 hi = __float2bfloat16(v);
            __nv_bfloat16 lo = __float2bfloat16(v - __bfloat162float(hi));
            int col = w * Esz + lane;
            d_gA[b * KTRIP + col]       = hi;
            d_gA[b * KTRIP + 256 + col] = hi;
            d_gA[b * KTRIP + 512 + col] = lo;
        }
        if (lane >= 50 && lane < 56 && w == 0) {
            int col = 200 + lane;   // 250..255
            d_gA[b * KTRIP + col]       = z;
            d_gA[b * KTRIP + 256 + col] = z;
            d_gA[b * KTRIP + 512 + col] = z;
        }
        __syncthreads();
    }
}

// ---------------- kernel 4: fc1 mma.sync bf16, 3-stage cp.async pipeline ------
// CTA 128x128, K=768 in 12 slabs of 64 bf16; 8 warps = 2(M)x4(N), warp 64x32.
// smem: 3 stages x (A 16KB + B 16KB) = 96KB. Epilogue emits h as bf16 hi/lo.
#define FC1_SMEM 98304
__global__ __launch_bounds__(256) void k_fc1m(const float* __restrict__ b1) {
    extern __shared__ __align__(1024) char smc[];
    uint32_t sbase = smem_u32(smc);
    int tid = threadIdx.x;
    int lane = tid & 31, warp = tid >> 5;
    int wm = warp & 1, wn = warp >> 1;
    int bm = blockIdx.y << 7, bn = blockIdx.x << 7;

    float acc[4][4][4];
#pragma unroll
    for (int i = 0; i < 4; ++i)
#pragma unroll
        for (int j = 0; j < 4; ++j)
#pragma unroll
            for (int q = 0; q < 4; ++q) acc[i][j][q] = 0.f;

    const char* gA = (const char*)d_gA;
    const char* gB = (const char*)d_w1B;

    int lrow  = (lane & 7) + ((lane >> 3) & 1) * 8;
    int lchnk = (lane >> 4) << 4;
    uint32_t lsw = (uint32_t)((lane & 7) << 4);

    auto stage = [&](int s, int buf) {
        uint32_t ab = sbase + buf * 32768;
        uint32_t bb = ab + 16384;
        int koff = s * 128;
#pragma unroll
        for (int i = 0; i < 4; ++i) {
            int idx = tid + (i << 8);
            int r = idx >> 3, c = (idx & 7) << 4;
            cp16(ab + SWZ128(r * 128 + c), gA + (size_t)(bm + r) * (KTRIP * 2) + koff + c);
        }
#pragma unroll
        for (int i = 0; i < 4; ++i) {
            int idx = tid + (i << 8);
            int r = idx >> 3, c = (idx & 7) << 4;
            cp16(bb + SWZ128(r * 128 + c), gB + (size_t)(bn + r) * (KTRIP * 2) + koff + c);
        }
    };

    stage(0, 0); CP_COMMIT();
    stage(1, 1); CP_COMMIT();

    for (int s = 0; s < 12; ++s) {
        int buf = s - (s / 3) * 3;    // s % 3
        if (s + 2 < 12) {
            int nb = (s + 2) - ((s + 2) / 3) * 3;
            stage(s + 2, nb); CP_COMMIT(); CP_WAIT(2);
        } else {
            CP_WAIT(0);
        }
        __syncthreads();

        uint32_t ab = sbase + buf * 32768;
        uint32_t bb = ab + 16384;
        uint32_t arow[4], brow[2];
#pragma unroll
        for (int mt = 0; mt < 4; ++mt)
            arow[mt] = ab + (uint32_t)((wm << 6) + (mt << 4) + lrow) * 128;
#pragma unroll
        for (int np = 0; np < 2; ++np)
            brow[np] = bb + (uint32_t)((wn << 5) + (np << 4) + lrow) * 128;

#pragma unroll
        for (int kb = 0; kb < 4; ++kb) {
            uint32_t koffb = (uint32_t)(kb * 32 + lchnk) ^ lsw;
            uint32_t af[4][4];
#pragma unroll
            for (int mt = 0; mt < 4; ++mt) ldm_x4(af[mt], arow[mt] + koffb);
            uint32_t bf[2][4];
#pragma unroll
            for (int np = 0; np < 2; ++np) ldm_x4(bf[np], brow[np] + koffb);
#pragma unroll
            for (int mt = 0; mt < 4; ++mt) {
#pragma unroll
                for (int np = 0; np < 2; ++np) {
                    mma16816(acc[mt][np * 2],     af[mt], bf[np][0], bf[np][2]);
                    mma16816(acc[mt][np * 2 + 1], af[mt], bf[np][1], bf[np][3]);
                }
            }
        }
        __syncthreads();
    }

    // epilogue: tanh, split to bf16 hi/lo, store
    int r0 = lane >> 2, c0 = (lane & 3) << 1;
#pragma unroll
    for (int mt = 0; mt < 4; ++mt) {
        int row = bm + (wm << 6) + (mt << 4) + r0;
#pragma unroll
        for (int nt = 0; nt < 4; ++nt) {
            int col = bn + (wn << 5) + (nt << 3) + c0;
            float bias0 = b1[col], bias1 = b1[col + 1];
#pragma unroll
            for (int half = 0; half < 2; ++half) {
                size_t off = (size_t)(row + half * 8) * Hsz + col;
                float t0 = tanhf(acc[mt][nt][half * 2 + 0] + bias0);
                float t1 = tanhf(acc[mt][nt][half * 2 + 1] + bias1);
                __nv_bfloat16 h0 = __float2bfloat16(t0);
                __nv_bfloat16 h1 = __float2bfloat16(t1);
                __nv_bfloat162 vh; vh.x = h0; vh.y = h1;
                __nv_bfloat162 vl;
                vl.x = __float2bfloat16(t0 - __bfloat162float(h0));
                vl.y = __float2bfloat16(t1 - __bfloat162float(h1));
                *(__nv_bfloat162*)(d_hh + off) = vh;
                *(__nv_bfloat162*)(d_hl + off) = vl;
            }
        }
    }
}

// ---------------- kernel 5: fc2 mma.sync bf16 split + fused softmax ------------
// CTA 128 rows x 64 cols, K=4096 in 64 slabs of 64; 8 warps = 4(M)x2(N), warp 32x32.
// smem: 2 stages x (Ahi 16K + Alo 16K + Bhi 8K + Blo 8K) = 96KB.
#define FC2_SMEM 98304
__global__ __launch_bounds__(256) void k_fc2m(float* __restrict__ out) {
    extern __shared__ __align__(1024) char sm2[];
    uint32_t sbase = smem_u32(sm2);
    int tid = threadIdx.x;
    int lane = tid & 31, warp = tid >> 5;
    int wm = warp & 3, wn = warp >> 2;     // 4(M) x 2(N)
    int bm = blockIdx.x << 7;

    float acc[2][4][4];
#pragma unroll
    for (int i = 0; i < 2; ++i)
#pragma unroll
        for (int j = 0; j < 4; ++j)
#pragma unroll
            for (int q = 0; q < 4; ++q) acc[i][j][q] = 0.f;

    const char* gAh = (const char*)d_hh;
    const char* gAl = (const char*)d_hl;
    const char* gBh = (const char*)d_w2h;
    const char* gBl = (const char*)d_w2l;

    int lrow  = (lane & 7) + ((lane >> 3) & 1) * 8;
    int lchnk = (lane >> 4) << 4;
    uint32_t lsw = (uint32_t)((lane & 7) << 4);

    auto stage = [&](int s, int buf) {
        uint32_t base = sbase + buf * 49152;
        int koff = s * 128;
#pragma unroll
        for (int i = 0; i < 4; ++i) {                       // A hi: 128 rows
            int idx = tid + (i << 8);
            int r = idx >> 3, c = (idx & 7) << 4;
            size_t g = (size_t)(bm + r) * (Hsz * 2) + koff + c;
            cp16(base + SWZ128(r * 128 + c), gAh + g);
            cp16(base + 16384 + SWZ128(r * 128 + c), gAl + g);
        }
#pragma unroll
        for (int i = 0; i < 2; ++i) {                       // B hi/lo: 64 rows
            int idx = tid + (i << 8);
            int r = idx >> 3, c = (idx & 7) << 4;
            size_t g = (size_t)r * (Hsz * 2) + koff + c;
            cp16(base + 32768 + SWZ128(r * 128 + c), gBh + g);
            cp16(base + 40960 + SWZ128(r * 128 + c), gBl + g);
        }
    };

    stage(0, 0); CP_COMMIT();

    for (int s = 0; s < 64; ++s) {
        int buf = s & 1;
        if (s < 63) { stage(s + 1, buf ^ 1); CP_COMMIT(); CP_WAIT(1); }
        else        { CP_WAIT(0); }
        __syncthreads();

        uint32_t ah = sbase + buf * 49152;
        uint32_t al = ah + 16384;
        uint32_t bh = ah + 32768;
        uint32_t bl = ah + 40960;
        uint32_t arh[2], arl[2], brh[2], brl[2];
#pragma unroll
        for (int mt = 0; mt < 2; ++mt) {
            uint32_t ro = (uint32_t)((wm << 5) + (mt << 4) + lrow) * 128;
            arh[mt] = ah + ro; arl[mt] = al + ro;
        }
#pragma unroll
        for (int np = 0; np < 2; ++np) {
            uint32_t ro = (uint32_t)((wn << 5) + (np << 4) + lrow) * 128;
            brh[np] = bh + ro; brl[np] = bl + ro;
        }

#pragma unroll
        for (int kb = 0; kb < 4; ++kb) {
            uint32_t koffb = (uint32_t)(kb * 32 + lchnk) ^ lsw;
            uint32_t afh[2][4], afl[2][4], bfh[2][4], bfl[2][4];
#pragma unroll
            for (int mt = 0; mt < 2; ++mt) { ldm_x4(afh[mt], arh[mt] + koffb); ldm_x4(afl[mt], arl[mt] + koffb); }
#pragma unroll
            for (int np = 0; np < 2; ++np) { ldm_x4(bfh[np], brh[np] + koffb); ldm_x4(bfl[np], brl[np] + koffb); }
#pragma unroll
            for (int mt = 0; mt < 2; ++mt) {
#pragma unroll
                for (int np = 0; np < 2; ++np) {
                    mma16816(acc[mt][np * 2],     afh[mt], bfh[np][0], bfh[np][2]);
                    mma16816(acc[mt][np * 2 + 1], afh[mt], bfh[np][1], bfh[np][3]);
                    mma16816(acc[mt][np * 2],     afh[mt], bfl[np][0], bfl[np][2]);
                    mma16816(acc[mt][np * 2 + 1], afh[mt], bfl[np][1], bfl[np][3]);
                    mma16816(acc[mt][np * 2],     afl[mt], bfh[np][0], bfh[np][2]);
                    mma16816(acc[mt][np * 2 + 1], afl[mt], bfh[np][1], bfh[np][3]);
                }
            }
        }
        __syncthreads();
    }

    // scores -> smem, then per-row softmax
    float (*sc)[66] = (float(*)[66])sm2;
    int r0 = lane >> 2, c0 = (lane & 3) << 1;
#pragma unroll
    for (int mt = 0; mt < 2; ++mt) {
        int rr = (wm << 5) + (mt << 4) + r0;
#pragma unroll
        for (int nt = 0; nt < 4; ++nt) {
            int cc = (wn << 5) + (nt << 3) + c0;
            float b0 = d_b2p[cc], b1v = d_b2p[cc + 1];
            sc[rr][cc]         = acc[mt][nt][0] + b0;
            sc[rr][cc + 1]     = acc[mt][nt][1] + b1v;
            sc[rr + 8][cc]     = acc[mt][nt][2] + b0;
            sc[rr + 8][cc + 1] = acc[mt][nt][3] + b1v;
        }
    }
    __syncthreads();

    if (tid < 128) {
        int r = tid;
        float mx = -1e30f;
#pragma unroll
        for (int c = 0; c < Osz; ++c) mx = fmaxf(mx, sc[r][c]);
        float ssum = 0.f;
        float ev[Osz];
#pragma unroll
        for (int c = 0; c < Osz; ++c) { ev[c] = expf(sc[r][c] - mx); ssum += ev[c]; }
        float inv = 1.f / ssum;
        float* orow = out + (size_t)(bm + r) * Osz;
#pragma unroll
        for (int c = 0; c < Osz; c += 2) {
            float2 o; o.x = ev[c] * inv; o.y = ev[c + 1] * inv;
            *(float2*)(orow + c) = o;
        }
    }
}

// ---------------- launcher ----------------
extern "C" void kernel_launch(void* const* d_in, const int* in_sizes, int n_in,
                              void* d_out, int out_size) {
    const int *x = 0, *w2c = 0;
    const float *wemb = 0, *cemb = 0, *convw = 0, *convb = 0;
    const float *w1 = 0, *b1 = 0, *w2 = 0, *b2 = 0;
    int seen50 = 0;
    for (int i = 0; i < n_in; ++i) {
        int s = in_sizes[i];
        if      (s == Bsz * Wsz)     x     = (const int*)d_in[i];
        else if (s == Vsz * Lsz)     w2c   = (const int*)d_in[i];
        else if (s == Vsz * Esz)     wemb  = (const float*)d_in[i];
        else if (s == Csz * Esz)     cemb  = (const float*)d_in[i];
        else if (s == Esz * Esz * 3) convw = (const float*)d_in[i];
        else if (s == Hsz * 250)     w1    = (const float*)d_in[i];
        else if (s == Hsz)           b1    = (const float*)d_in[i];
        else if (s == Osz * Hsz)     w2    = (const float*)d_in[i];
        else if (s == 50) {
            if (seen50++ == 0) convb = (const float*)d_in[i];
            else               b2    = (const float*)d_in[i];
        }
    }
    float* out = (float*)d_out;

    static bool attr_set = false;
    if (!attr_set) {
        cudaFuncSetAttribute(k_feat,  cudaFuncAttributeMaxDynamicSharedMemorySize, 80000);
        cudaFuncSetAttribute(k_fc1m,  cudaFuncAttributeMaxDynamicSharedMemorySize, FC1_SMEM);
        cudaFuncSetAttribute(k_fc2m,  cudaFuncAttributeMaxDynamicSharedMemorySize, FC2_SMEM);
        attr_set = true;
    }

    // prep (tiny)
    k_proj  <<<Csz, 160>>>(convw, cemb);
    k_prepw1<<<Hsz, 256>>>(w1);
    k_prepw2<<<(64 * Hsz) / 256, 256>>>(w2, b2);

    // features -> split-bf16 A''
    size_t feat_smem = (19200 + 64 + 8 * Lsz) * sizeof(float);
    k_feat<<<NW / 32, 512, feat_smem>>>(x, w2c, wemb, convb);

    // fc1: mma.sync bf16 split GEMM, M=16384 N=4096 K=768 (3-stage pipeline)
    k_fc1m<<<dim3(Hsz / 128, Bsz / 128), 256, FC1_SMEM>>>(b1);

    // fc2: mma.sync bf16 split GEMM + fused softmax
    k_fc2m<<<Bsz / 128, 256, FC2_SMEM>>>(out);
}

// round 8
// speedup vs baseline: 2.4762x; 1.1176x over previous
#include <cuda_runtime.h>
#include <cuda_bf16.h>
#include <math.h>
#include <stdint.h>

// ---------------- problem constants ----------------
#define Bsz   16384
#define Wsz   5
#define Lsz   20
#define Esz   50
#define Vsz   100000
#define Csz   128
#define Hsz   4096
#define Osz   50
#define NW    (Bsz*Wsz)

// fc1 split-bf16 GEMM: K'' = 3*256 (hi*hi | hi*lo | lo*hi baked into K)
#define KTRIP 768

// ---------------- device scratch ----------------
__device__ float d_proj[3 * Csz * Esz];
__device__ __align__(16) __nv_bfloat16 d_gA[Bsz * KTRIP];     // 25 MB  A'' bf16
__device__ __align__(16) __nv_bfloat16 d_w1B[Hsz * KTRIP];    // 6 MB   B'' bf16
__device__ __align__(16) __nv_bfloat16 d_w2h[64 * Hsz];       // 512 KB
__device__ __align__(16) __nv_bfloat16 d_w2l[64 * Hsz];       // 512 KB
__device__ float d_b2p[64];
__device__ float d_logits[Bsz * 64];                          // 4 MB

// ---------------- helpers ----------------
__device__ __forceinline__ uint32_t smem_u32(const void* p) {
    uint32_t a;
    asm("{ .reg .u64 t; cvta.to.shared.u64 t, %1; cvt.u32.u64 %0, t; }" : "=r"(a) : "l"(p));
    return a;
}
#define SWZ128(o) ((o) ^ ((((uint32_t)(o)) >> 3) & 0x70))
__device__ __forceinline__ void cp16(uint32_t saddr, const void* g) {
    asm volatile("cp.async.cg.shared.global [%0], [%1], 16;" :: "r"(saddr), "l"(g));
}
#define CP_COMMIT() asm volatile("cp.async.commit_group;" ::: "memory")
#define CP_WAIT(n)  asm volatile("cp.async.wait_group %0;" :: "n"(n) : "memory")

__device__ __forceinline__ void ldm_x4(uint32_t* r, uint32_t saddr) {
    asm volatile("ldmatrix.sync.aligned.m8n8.x4.shared.b16 {%0,%1,%2,%3}, [%4];"
                 : "=r"(r[0]), "=r"(r[1]), "=r"(r[2]), "=r"(r[3]) : "r"(saddr));
}
__device__ __forceinline__ void mma16816(float* c, const uint32_t* a, uint32_t b0, uint32_t b1) {
    asm volatile("mma.sync.aligned.m16n8k16.row.col.f32.bf16.bf16.f32 "
                 "{%0,%1,%2,%3}, {%4,%5,%6,%7}, {%8,%9}, {%0,%1,%2,%3};"
                 : "+f"(c[0]), "+f"(c[1]), "+f"(c[2]), "+f"(c[3])
                 : "r"(a[0]), "r"(a[1]), "r"(a[2]), "r"(a[3]), "r"(b0), "r"(b1));
}

// ---------------- kernel 0: zero logits ----------------
__global__ void k_zero() {
    d_logits[blockIdx.x * 1024 + threadIdx.x] = 0.f;
}

// ---------------- kernel 1: proj tables ----------------
__global__ void k_proj(const float* __restrict__ conv_w, const float* __restrict__ char_emb) {
    int tid = threadIdx.x;
    if (tid >= 150) return;
    int k = tid / 50, e = tid % 50;
    int c = blockIdx.x;
    float acc = 0.f;
#pragma unroll
    for (int i = 0; i < Esz; ++i)
        acc += conv_w[(e * Esz + i) * 3 + k] * char_emb[c * Esz + i];
    d_proj[k * (Csz * Esz) + c * Esz + e] = acc;
}

// ---------------- kernel 2a: fc1_w -> split-bf16 K-tripled [4096,768] ----------------
__global__ void k_prepw1(const float* __restrict__ w1) {
    int idx = blockIdx.x * blockDim.x + threadIdx.x;
    int n = idx >> 8, k = idx & 255;
    float v = (k < 250) ? w1[n * 250 + k] : 0.f;
    __nv_bfloat16 hi = __float2bfloat16(v);
    __nv_bfloat16 lo = __float2bfloat16(v - __bfloat162float(hi));
    d_w1B[n * KTRIP + k]       = hi;
    d_w1B[n * KTRIP + 256 + k] = lo;
    d_w1B[n * KTRIP + 512 + k] = hi;
}

// ---------------- kernel 2b: fc2_w -> split bf16 [64,4096] + bias pad ----------------
__global__ void k_prepw2(const float* __restrict__ w2, const float* __restrict__ b2) {
    int idx = blockIdx.x * blockDim.x + threadIdx.x;   // < 64*4096
    int o = idx >> 12;
    float v = (o < 50) ? w2[o * Hsz + (idx & 4095)] : 0.f;
    __nv_bfloat16 hi = __float2bfloat16(v);
    __nv_bfloat16 lo = __float2bfloat16(v - __bfloat162float(hi));
    d_w2h[idx] = hi;
    d_w2l[idx] = lo;
    if (idx < 64) d_b2p[idx] = (idx < 50) ? b2[idx] : 0.f;
}

// ---------------- kernel 3: features (warp-per-word) -> split-bf16 A'' ----------------
__global__ __launch_bounds__(256) void k_feat(const int* __restrict__ x, const int* __restrict__ w2c,
                                              const float* __restrict__ wemb, const float* __restrict__ convb) {
    extern __shared__ float smf[];
    float* sp  = smf;            // 19200 floats: proj tables
    float* scb = smf + 19200;    // 64: conv bias

    int tid = threadIdx.x;
    for (int i = tid; i < 4800; i += 256)
        ((float4*)sp)[i] = ((const float4*)d_proj)[i];
    if (tid < 50) scb[tid] = convb[tid];
    __syncthreads();

    int lane = tid & 31, warp = tid >> 5;
    int base = blockIdx.x * 32 + warp * 4;
    bool act = lane < 25;
    int e2 = lane << 1;

    for (int it = 0; it < 4; ++it) {
        int widx = base + it;
        int xv = x[widx];
        int cidreg = 0;
        if (lane < Lsz) cidreg = w2c[xv * Lsz + lane];

        float m0 = -1e30f, m1 = -1e30f;
        int cp = 0;
        int cc = __shfl_sync(0xffffffffu, cidreg, 0);
#pragma unroll
        for (int l = 0; l < Lsz; ++l) {
            int cn = (l < Lsz - 1) ? __shfl_sync(0xffffffffu, cidreg, l + 1) : 0;
            if (act) {
                float2 s0 = *(const float2*)(sp + cp * 50 + e2);
                float2 s1 = *(const float2*)(sp + 6400 + cc * 50 + e2);
                float2 s2 = *(const float2*)(sp + 12800 + cn * 50 + e2);
                m0 = fmaxf(m0, s0.x + s1.x + s2.x);
                m1 = fmaxf(m1, s0.y + s1.y + s2.y);
            }
            cp = cc; cc = cn;
        }

        int b = widx / Wsz, w = widx - b * Wsz;
        if (act) {
            float2 we = *(const float2*)(wemb + xv * 50 + e2);
            float2 cb = *(const float2*)(scb + e2);
            float v0 = we.x + m0 + cb.x;
            float v1 = we.y + m1 + cb.y;
            __nv_bfloat16 h0 = __float2bfloat16(v0);
            __nv_bfloat16 h1 = __float2bfloat16(v1);
            __nv_bfloat162 vh; vh.x = h0; vh.y = h1;
            __nv_bfloat162 vl;
            vl.x = __float2bfloat16(v0 - __bfloat162float(h0));
            vl.y = __float2bfloat16(v1 - __bfloat162float(h1));
            int col = w * 50 + e2;
            *(__nv_bfloat162*)(d_gA + b * KTRIP + col)       = vh;
            *(__nv_bfloat162*)(d_gA + b * KTRIP + 256 + col) = vh;
            *(__nv_bfloat162*)(d_gA + b * KTRIP + 512 + col) = vl;
        } else if (lane < 28 && w == 0) {          // zero pads cols [250,256)
            int col = 250 + ((lane - 25) << 1);
            __nv_bfloat162 z2; z2.x = __float2bfloat16(0.f); z2.y = z2.x;
            *(__nv_bfloat162*)(d_gA + b * KTRIP + col)       = z2;
            *(__nv_bfloat162*)(d_gA + b * KTRIP + 256 + col) = z2;
            *(__nv_bfloat162*)(d_gA + b * KTRIP + 512 + col) = z2;
        }
    }
}

// ---------------- kernel 4: fused fc1 + fc2-partial --------------------------
// Mainloop: h-tile = tanh(A''@B''^T + b1) 128x128, K=768 (mma.sync, 3-stage cp.async).
// Epilogue: h hi/lo -> smem; logits[128x64] += hhi*w2h + hhi*w2l + hlo*w2h (K=128);
// atomicAdd into d_logits. h never touches HBM.
// smem 96KB: 3x32KB pipeline; epilogue reuse: hhi [0,32K), hlo [32K,64K), w2 [64K,96K).
#define FC1_SMEM 98304
__global__ __launch_bounds__(256) void k_fc1f(const float* __restrict__ b1) {
    extern __shared__ __align__(1024) char smc[];
    uint32_t sbase = smem_u32(smc);
    int tid = threadIdx.x;
    int lane = tid & 31, warp = tid >> 5;
    int wm = warp & 1, wn = warp >> 1;
    int bm = blockIdx.y << 7, bn = blockIdx.x << 7;

    float acc[4][4][4];
#pragma unroll
    for (int i = 0; i < 4; ++i)
#pragma unroll
        for (int j = 0; j < 4; ++j)
#pragma unroll
            for (int q = 0; q < 4; ++q) acc[i][j][q] = 0.f;

    const char* gA = (const char*)d_gA;
    const char* gB = (const char*)d_w1B;

    int lrow  = (lane & 7) + ((lane >> 3) & 1) * 8;
    int lchnk = (lane >> 4) << 4;
    uint32_t lsw = (uint32_t)((lane & 7) << 4);

    auto stage = [&](int s, int buf) {
        uint32_t ab = sbase + buf * 32768;
        uint32_t bb = ab + 16384;
        int koff = s * 128;
#pragma unroll
        for (int i = 0; i < 4; ++i) {
            int idx = tid + (i << 8);
            int r = idx >> 3, c = (idx & 7) << 4;
            cp16(ab + SWZ128(r * 128 + c), gA + (size_t)(bm + r) * (KTRIP * 2) + koff + c);
        }
#pragma unroll
        for (int i = 0; i < 4; ++i) {
            int idx = tid + (i << 8);
            int r = idx >> 3, c = (idx & 7) << 4;
            cp16(bb + SWZ128(r * 128 + c), gB + (size_t)(bn + r) * (KTRIP * 2) + koff + c);
        }
    };

    stage(0, 0); CP_COMMIT();
    stage(1, 1); CP_COMMIT();

    for (int s = 0; s < 12; ++s) {
        int buf = s - (s / 3) * 3;
        if (s + 2 < 12) {
            int nb = (s + 2) - ((s + 2) / 3) * 3;
            stage(s + 2, nb); CP_COMMIT(); CP_WAIT(2);
        } else {
            CP_WAIT(0);
        }
        __syncthreads();

        uint32_t ab = sbase + buf * 32768;
        uint32_t bb = ab + 16384;
        uint32_t arow[4], brow[2];
#pragma unroll
        for (int mt = 0; mt < 4; ++mt)
            arow[mt] = ab + (uint32_t)((wm << 6) + (mt << 4) + lrow) * 128;
#pragma unroll
        for (int np = 0; np < 2; ++np)
            brow[np] = bb + (uint32_t)((wn << 5) + (np << 4) + lrow) * 128;

#pragma unroll
        for (int kb = 0; kb < 4; ++kb) {
            uint32_t koffb = (uint32_t)(kb * 32 + lchnk) ^ lsw;
            uint32_t af[4][4];
#pragma unroll
            for (int mt = 0; mt < 4; ++mt) ldm_x4(af[mt], arow[mt] + koffb);
            uint32_t bf[2][4];
#pragma unroll
            for (int np = 0; np < 2; ++np) ldm_x4(bf[np], brow[np] + koffb);
#pragma unroll
            for (int mt = 0; mt < 4; ++mt) {
#pragma unroll
                for (int np = 0; np < 2; ++np) {
                    mma16816(acc[mt][np * 2],     af[mt], bf[np][0], bf[np][2]);
                    mma16816(acc[mt][np * 2 + 1], af[mt], bf[np][1], bf[np][3]);
                }
            }
        }
        __syncthreads();
    }

    // ---- epilogue phase 1: issue w2 slice loads into [64K, 96K) ----
    {
        const char* gW2h = (const char*)d_w2h;
        const char* gW2l = (const char*)d_w2l;
#pragma unroll
        for (int i = 0; i < 8; ++i) {
            int idx = tid + (i << 8);
            int hl = idx >> 10, rem = idx & 1023;
            int j = rem >> 9, rem2 = rem & 511;
            int o = rem2 >> 3, c = (rem2 & 7) << 4;
            const char* src = (hl ? gW2l : gW2h) + (size_t)o * 8192 + (size_t)(bn + (j << 6)) * 2 + c;
            cp16(sbase + 65536 + hl * 16384 + (j << 13) + SWZ128(o * 128 + c), src);
        }
        CP_COMMIT();
    }

    // ---- epilogue phase 2: tanh + split, h tile -> smem [0, 64K) ----
    int r0 = lane >> 2, c0 = (lane & 3) << 1;
#pragma unroll
    for (int mt = 0; mt < 4; ++mt) {
#pragma unroll
        for (int nt = 0; nt < 4; ++nt) {
            int col = (wn << 5) + (nt << 3) + c0;       // 0..127 local
            float bias0 = b1[bn + col], bias1 = b1[bn + col + 1];
            int slab = col >> 6, inner = col & 63;
#pragma unroll
            for (int half = 0; half < 2; ++half) {
                int rowl = (wm << 6) + (mt << 4) + r0 + (half << 3);
                float t0 = tanhf(acc[mt][nt][half * 2 + 0] + bias0);
                float t1 = tanhf(acc[mt][nt][half * 2 + 1] + bias1);
                __nv_bfloat16 h0 = __float2bfloat16(t0);
                __nv_bfloat16 h1 = __float2bfloat16(t1);
                __nv_bfloat162 vh; vh.x = h0; vh.y = h1;
                __nv_bfloat162 vl;
                vl.x = __float2bfloat16(t0 - __bfloat162float(h0));
                vl.y = __float2bfloat16(t1 - __bfloat162float(h1));
                uint32_t off = SWZ128((uint32_t)rowl * 128 + inner * 2);
                *(__nv_bfloat162*)(smc + (slab << 14) + off)         = vh;
                *(__nv_bfloat162*)(smc + 32768 + (slab << 14) + off) = vl;
            }
        }
    }
    CP_WAIT(0);
    __syncthreads();

    // ---- epilogue phase 3: mini GEMM, logits partial [128x64], K=128 ----
    float a2[4][2][4];
#pragma unroll
    for (int i = 0; i < 4; ++i)
#pragma unroll
        for (int j = 0; j < 2; ++j)
#pragma unroll
            for (int q = 0; q < 4; ++q) a2[i][j][q] = 0.f;

#pragma unroll
    for (int slab = 0; slab < 2; ++slab) {
        uint32_t ahb = sbase + (slab << 14);
        uint32_t alb = ahb + 32768;
        uint32_t bhb = sbase + 65536 + (slab << 13);
        uint32_t blb = bhb + 16384;
        uint32_t brow = (uint32_t)((wn << 4) + lrow) * 128;
#pragma unroll
        for (int kb = 0; kb < 4; ++kb) {
            uint32_t koffb = (uint32_t)(kb * 32 + lchnk) ^ lsw;
            uint32_t bh[4], bl[4];
            ldm_x4(bh, bhb + brow + koffb);
            ldm_x4(bl, blb + brow + koffb);
#pragma unroll
            for (int mt = 0; mt < 4; ++mt) {
                uint32_t arow = (uint32_t)((wm << 6) + (mt << 4) + lrow) * 128;
                uint32_t ah[4], al[4];
                ldm_x4(ah, ahb + arow + koffb);
                ldm_x4(al, alb + arow + koffb);
                mma16816(a2[mt][0], ah, bh[0], bh[2]);
                mma16816(a2[mt][1], ah, bh[1], bh[3]);
                mma16816(a2[mt][0], ah, bl[0], bl[2]);
                mma16816(a2[mt][1], ah, bl[1], bl[3]);
                mma16816(a2[mt][0], al, bh[0], bh[2]);
                mma16816(a2[mt][1], al, bh[1], bh[3]);
            }
        }
    }

    // ---- epilogue phase 4: atomic accumulate into d_logits ----
#pragma unroll
    for (int mt = 0; mt < 4; ++mt) {
#pragma unroll
        for (int nt = 0; nt < 2; ++nt) {
            int colg = (wn << 4) + (nt << 3) + c0;
#pragma unroll
            for (int half = 0; half < 2; ++half) {
                int rowg = bm + (wm << 6) + (mt << 4) + r0 + (half << 3);
                atomicAdd(&d_logits[rowg * 64 + colg],     a2[mt][nt][half * 2 + 0]);
                atomicAdd(&d_logits[rowg * 64 + colg + 1], a2[mt][nt][half * 2 + 1]);
            }
        }
    }
}

// ---------------- kernel 5: softmax over logits ----------------
__global__ __launch_bounds__(256) void k_smax(float* __restrict__ out) {
    int r = blockIdx.x * 256 + threadIdx.x;   // 64 blocks x 256 = 16384 rows
    const float* lr = d_logits + r * 64;
    float v[Osz];
    float mx = -1e30f;
#pragma unroll
    for (int c = 0; c < Osz; ++c) {
        v[c] = lr[c] + d_b2p[c];
        mx = fmaxf(mx, v[c]);
    }
    float ssum = 0.f;
#pragma unroll
    for (int c = 0; c < Osz; ++c) { v[c] = expf(v[c] - mx); ssum += v[c]; }
    float inv = 1.f / ssum;
    float* orow = out + (size_t)r * Osz;
#pragma unroll
    for (int c = 0; c < Osz; c += 2) {
        float2 o; o.x = v[c] * inv; o.y = v[c + 1] * inv;
        *(float2*)(orow + c) = o;
    }
}

// ---------------- launcher ----------------
extern "C" void kernel_launch(void* const* d_in, const int* in_sizes, int n_in,
                              void* d_out, int out_size) {
    const int *x = 0, *w2c = 0;
    const float *wemb = 0, *cemb = 0, *convw = 0, *convb = 0;
    const float *w1 = 0, *b1 = 0, *w2 = 0, *b2 = 0;
    int seen50 = 0;
    for (int i = 0; i < n_in; ++i) {
        int s = in_sizes[i];
        if      (s == Bsz * Wsz)     x     = (const int*)d_in[i];
        else if (s == Vsz * Lsz)     w2c   = (const int*)d_in[i];
        else if (s == Vsz * Esz)     wemb  = (const float*)d_in[i];
        else if (s == Csz * Esz)     cemb  = (const float*)d_in[i];
        else if (s == Esz * Esz * 3) convw = (const float*)d_in[i];
        else if (s == Hsz * 250)     w1    = (const float*)d_in[i];
        else if (s == Hsz)           b1    = (const float*)d_in[i];
        else if (s == Osz * Hsz)     w2    = (const float*)d_in[i];
        else if (s == 50) {
            if (seen50++ == 0) convb = (const float*)d_in[i];
            else               b2    = (const float*)d_in[i];
        }
    }
    float* out = (float*)d_out;

    static bool attr_set = false;
    if (!attr_set) {
        cudaFuncSetAttribute(k_feat,  cudaFuncAttributeMaxDynamicSharedMemorySize, 80000);
        cudaFuncSetAttribute(k_fc1f,  cudaFuncAttributeMaxDynamicSharedMemorySize, FC1_SMEM);
        attr_set = true;
    }

    // zero logits + prep (tiny)
    k_zero  <<<1024, 1024>>>();
    k_proj  <<<Csz, 160>>>(convw, cemb);
    k_prepw1<<<Hsz, 256>>>(w1);
    k_prepw2<<<(64 * Hsz) / 256, 256>>>(w2, b2);

    // features -> split-bf16 A''  (warp-per-word)
    size_t feat_smem = 19264 * sizeof(float);
    k_feat<<<NW / 32, 256, feat_smem>>>(x, w2c, wemb, convb);

    // fused fc1 + fc2-partial (atomics into d_logits)
    k_fc1f<<<dim3(Hsz / 128, Bsz / 128), 256, FC1_SMEM>>>(b1);

    // softmax
    k_smax<<<Bsz / 256, 256>>>(out);
}